// round 11
// baseline (speedup 1.0000x reference)
#include <cuda_runtime.h>
#include <cstdint>

// x: [B, C, L, L] fp32, B=128, C=3, L=256, N=4 boxes per sample
// X/Y/W/H: [N, B] int32
// out[b,c,y,x] = inside-any-box(b,y,x) ? 0 : x[b,c,y,x]
// Mask depends on (b, y, x) only — compute once, apply to all 3 channels.
//
// FINAL CONVERGED FORM (10 rounds): one thread per (b, y, col-quad),
// lane-contiguous float4 accesses, 3 far-apart channel planes per thread
// (MLP=3 with perfect coalescing), __ldcs/__stcs streaming hints, pure 32-bit
// indexing, 256-thread blocks. Best measured: 26.50us kernel = 7.6 TB/s
// aggregate R+W = ~95% of HBM duplex spec.
//
// Falsified variants (kernel us): 2-site 64-bit (27.17), 2-site 32-bit
// (27.23, occ*MLP conserved), mask-first branch (28.22), plain stores/512thr
// (28.03), unsigned-range mask (28.10), adjacent-pair widening (33.22,
// breaks intra-warp contiguity).

#define BB 128
#define CC 3
#define LL 256
#define NN 4

#define CH4   (LL * LL / 4)          // 16384 float4 per channel plane
#define TOT4  (BB * CH4)             // 2,097,152 sites

__global__ __launch_bounds__(256)
void masking_kernel(const float4* __restrict__ x4,
                    const int* __restrict__ Xb,
                    const int* __restrict__ Yb,
                    const int* __restrict__ Wb,
                    const int* __restrict__ Hb,
                    float4* __restrict__ out4)
{
    int i4 = blockIdx.x * blockDim.x + threadIdx.x;   // [0, TOT4), exact grid

    int inner = i4 & (CH4 - 1);       // y*64 + col4 within one channel plane
    int b     = i4 >> 14;             // sample index (CH4 = 2^14)
    int col   = (i4 & 63) << 2;       // first column of this quad
    int y     = (i4 >> 6) & (LL - 1);

    int base = b * (CC * CH4) + inner;   // max 6.29M float4 -> fits in int32

    // Front-batch all 3 channel loads (MLP_p1 = 3), streaming hint (no reuse).
    float4 v0 = __ldcs(&x4[base]);
    float4 v1 = __ldcs(&x4[base + CH4]);
    float4 v2 = __ldcs(&x4[base + 2 * CH4]);

    // 4-bit column mask for cols [col, col+3], any of N boxes.
    unsigned m = 0u;
#pragma unroll
    for (int n = 0; n < NN; n++) {
        int xs = __ldg(&Xb[n * BB + b]);
        int ys = __ldg(&Yb[n * BB + b]);
        int w  = __ldg(&Wb[n * BB + b]);
        int h  = __ldg(&Hb[n * BB + b]);
        bool yin = (y >= ys) && (y <= ys + h);
        if (yin) {
            int xe = xs + w;
#pragma unroll
            for (int j = 0; j < 4; j++) {
                int c = col + j;
                m |= ((c >= xs) & (c <= xe)) ? (1u << j) : 0u;
            }
        }
    }

    if (m & 1u) { v0.x = 0.0f; v1.x = 0.0f; v2.x = 0.0f; }
    if (m & 2u) { v0.y = 0.0f; v1.y = 0.0f; v2.y = 0.0f; }
    if (m & 4u) { v0.z = 0.0f; v1.z = 0.0f; v2.z = 0.0f; }
    if (m & 8u) { v0.w = 0.0f; v1.w = 0.0f; v2.w = 0.0f; }

    __stcs(&out4[base],           v0);
    __stcs(&out4[base + CH4],     v1);
    __stcs(&out4[base + 2 * CH4], v2);
}

extern "C" void kernel_launch(void* const* d_in, const int* in_sizes, int n_in,
                              void* d_out, int out_size)
{
    const float4* x4 = (const float4*)d_in[0];
    const int* Xb = (const int*)d_in[1];
    const int* Yb = (const int*)d_in[2];
    const int* Wb = (const int*)d_in[3];
    const int* Hb = (const int*)d_in[4];
    float4* out4 = (float4*)d_out;

    const int threads = 256;
    const int blocks = TOT4 / threads;   // 8192, exact
    masking_kernel<<<blocks, threads>>>(x4, Xb, Yb, Wb, Hb, out4);
}

// round 12
// speedup vs baseline: 1.0064x; 1.0064x over previous
#include <cuda_runtime.h>
#include <cstdint>

// x: [B, C, L, L] fp32, B=128, C=3, L=256, N=4 boxes per sample
// X/Y/W/H: [N, B] int32
// out[b,c,y,x] = inside-any-box(b,y,x) ? 0 : x[b,c,y,x]
// Mask depends on (b, y, x) only — compute once, apply to all 3 channels.
//
// FINAL CONVERGED FORM (11 rounds of measurement): one thread per
// (b, y, col-quad), lane-contiguous float4 accesses, 3 far-apart channel
// planes per thread (MLP=3 with perfect coalescing), __ldcs/__stcs streaming
// hints, pure 32-bit indexing, 256-thread blocks.
//
// Measured: 26.50-27.58us kernel (run-to-run band) = 7.3-7.6 TB/s aggregate
// R+W = 91-95% of the 8 TB/s HBM3e spec. The kernel is at the DRAM duplex
// roofline; the residual gap is read/write turnaround, not SM-recoverable.
//
// Falsified variants (kernel us): 2-site 64-bit (27.17), 2-site 32-bit
// (27.23 — occ x MLP is conserved across splits), mask-first read-skip
// (28.22 — warp-granularity sectors defeat it), plain stores / 512-thr
// (28.03), unsigned-range mask (28.10 — more ALU than bool-ternary),
// adjacent-pair widening (33.22 — breaks intra-warp contiguity).

#define BB 128
#define CC 3
#define LL 256
#define NN 4

#define CH4   (LL * LL / 4)          // 16384 float4 per channel plane
#define TOT4  (BB * CH4)             // 2,097,152 sites

__global__ __launch_bounds__(256)
void masking_kernel(const float4* __restrict__ x4,
                    const int* __restrict__ Xb,
                    const int* __restrict__ Yb,
                    const int* __restrict__ Wb,
                    const int* __restrict__ Hb,
                    float4* __restrict__ out4)
{
    int i4 = blockIdx.x * blockDim.x + threadIdx.x;   // [0, TOT4), exact grid

    int inner = i4 & (CH4 - 1);       // y*64 + col4 within one channel plane
    int b     = i4 >> 14;             // sample index (CH4 = 2^14)
    int col   = (i4 & 63) << 2;       // first column of this quad
    int y     = (i4 >> 6) & (LL - 1);

    int base = b * (CC * CH4) + inner;   // max 6.29M float4 -> fits in int32

    // Front-batch all 3 channel loads (MLP_p1 = 3), streaming hint (no reuse).
    float4 v0 = __ldcs(&x4[base]);
    float4 v1 = __ldcs(&x4[base + CH4]);
    float4 v2 = __ldcs(&x4[base + 2 * CH4]);

    // 4-bit column mask for cols [col, col+3], any of N boxes.
    unsigned m = 0u;
#pragma unroll
    for (int n = 0; n < NN; n++) {
        int xs = __ldg(&Xb[n * BB + b]);
        int ys = __ldg(&Yb[n * BB + b]);
        int w  = __ldg(&Wb[n * BB + b]);
        int h  = __ldg(&Hb[n * BB + b]);
        bool yin = (y >= ys) && (y <= ys + h);
        if (yin) {
            int xe = xs + w;
#pragma unroll
            for (int j = 0; j < 4; j++) {
                int c = col + j;
                m |= ((c >= xs) & (c <= xe)) ? (1u << j) : 0u;
            }
        }
    }

    if (m & 1u) { v0.x = 0.0f; v1.x = 0.0f; v2.x = 0.0f; }
    if (m & 2u) { v0.y = 0.0f; v1.y = 0.0f; v2.y = 0.0f; }
    if (m & 4u) { v0.z = 0.0f; v1.z = 0.0f; v2.z = 0.0f; }
    if (m & 8u) { v0.w = 0.0f; v1.w = 0.0f; v2.w = 0.0f; }

    __stcs(&out4[base],           v0);
    __stcs(&out4[base + CH4],     v1);
    __stcs(&out4[base + 2 * CH4], v2);
}

extern "C" void kernel_launch(void* const* d_in, const int* in_sizes, int n_in,
                              void* d_out, int out_size)
{
    const float4* x4 = (const float4*)d_in[0];
    const int* Xb = (const int*)d_in[1];
    const int* Yb = (const int*)d_in[2];
    const int* Wb = (const int*)d_in[3];
    const int* Hb = (const int*)d_in[4];
    float4* out4 = (float4*)d_out;

    const int threads = 256;
    const int blocks = TOT4 / threads;   // 8192, exact
    masking_kernel<<<blocks, threads>>>(x4, Xb, Yb, Wb, Hb, out4);
}